// round 11
// baseline (speedup 1.0000x reference)
#include <cuda_runtime.h>
#include <math.h>

#define HBUF 25165824   // 12*65536*32 floats, channel-last [bv][p][c]

__device__ float g_hA[HBUF];
__device__ float g_hB[HBUF];
__device__ float g_hC[HBUF];
__device__ float g_spec[HBUF];
__device__ float g_Y[3145728];    // [row=bvc*256+x][32]  parity-permuted cols
__device__ float g_Z[3145728];    // [row=bvo*256+x][32]  (16 gr | 16 gi)
__device__ float g_X1[393216];
__device__ float g_X2[393216];
__device__ float g_Ef[8192];      // [y][32]: k<16 cos, k>=16 -sin
__device__ float g_EfP[4096];     // [u<128][m32] permuted folded fwd-y basis
__device__ float g_Dy[8192];      // [j32][y] inverse-y real basis
__device__ float g_E2P[8192];     // [x128][m64] parity-permuted fwd-x basis
__device__ float g_EIP[8192];     // [kk64][x128] parity-permuted inv-x basis /256
__device__ float g_W1T[8192];     // fc1t_w transposed [j256][c32]

typedef unsigned long long u64;

__device__ __forceinline__ u64 pk2(float lo, float hi) {
    u64 r; asm("mov.b64 %0,{%1,%2};" : "=l"(r) : "f"(lo), "f"(hi)); return r;
}
__device__ __forceinline__ void upk2(u64 v, float& lo, float& hi) {
    asm("mov.b64 {%0,%1},%2;" : "=f"(lo), "=f"(hi) : "l"(v));
}
__device__ __forceinline__ u64 fma2(u64 a, u64 b, u64 c) {
    u64 d; asm("fma.rn.f32x2 %0,%1,%2,%3;" : "=l"(d) : "l"(a), "l"(b), "l"(c)); return d;
}
__device__ __forceinline__ float gelu_f(float x) {
    return 0.5f * x * (1.0f + erff(x * 0.70710678118654752440f));
}
__device__ __forceinline__ float* bufsel(int s) {
    if (s == 0) return g_hA;
    if (s == 1) return g_hB;
    if (s == 2) return g_hC;
    return g_spec;
}

// ----------------- basis tables -----------------
__global__ void setup_basis() {
    int x = threadIdx.x;
    int t = blockIdx.x;
    if (t < 16) {
        int k = t;
        double sv, cv;
        sincospi(((double)(k * x)) / 128.0, &sv, &cv);
        g_Ef[x * 32 + k]      = (float)cv;
        g_Ef[x * 32 + 16 + k] = (float)(-sv);
        double cj = (k == 0) ? 1.0 : 2.0;
        g_Dy[k * 256 + x]        = (float)( cj * cv / 256.0);
        g_Dy[(16 + k) * 256 + x] = (float)(-cj * sv / 256.0);
    } else {
        int j = t - 16;
        int f = (j < 16) ? j : (224 + j);
        double sv, cv;
        sincospi(((double)(f * x)) / 128.0, &sv, &cv);
        if (x < 128) {
            int p = j & 1, jh = j >> 1;
            g_E2P[x * 64 + p * 32 + jh]      = (float)cv;
            g_E2P[x * 64 + p * 32 + 16 + jh] = (float)sv;
            int base = p * 32 + jh * 2;
            g_EIP[base * 128 + x]       = (float)(cv / 256.0);
            g_EIP[(base + 1) * 128 + x] = (float)(sv / 256.0);
        }
    }
}

// permuted folded forward-y basis (u<128): col(m) = ((m>>3)&1)*16 + 2*(m&7) + (m>>4)
__global__ void setup_perm() {
    int e = blockIdx.x * 256 + threadIdx.x;   // 0..4095
    int u = e >> 5, m = e & 31;
    int col = ((m >> 3) & 1) * 16 + 2 * (m & 7) + (m >> 4);
    g_EfP[e] = g_Ef[u * 32 + col];
}

__global__ void transposeW1(const float* __restrict__ w) {
    int t = blockIdx.x * 256 + threadIdx.x;
    int c = t >> 8, j = t & 255;
    g_W1T[j * 32 + c] = w[t];
}

// ----------------- fc0 lift (channel-last out) -----------------
__global__ void __launch_bounds__(256) fc0_kernel(const float* __restrict__ xin,
                                                  const float* __restrict__ w,
                                                  const float* __restrict__ b) {
    __shared__ float sW[384];
    __shared__ float sB[32];
    int tid = threadIdx.x;
    for (int i = tid; i < 384; i += 256) sW[i] = w[i];
    if (tid < 32) sB[tid] = b[tid];
    __syncthreads();
    int q = blockIdx.x * 256 + tid;
    int p = q & 65535;
    float xv[12];
    const float* xp = xin + (size_t)q * 10;
#pragma unroll
    for (int t = 0; t < 10; t++) xv[t] = xp[t];
    xv[10] = (float)(p >> 8) * (1.0f / 255.0f);
    xv[11] = (float)(p & 255) * (1.0f / 255.0f);
    float acc[32];
#pragma unroll
    for (int c = 0; c < 32; c++) {
        float a = sB[c];
#pragma unroll
        for (int t = 0; t < 12; t++) a += xv[t] * sW[t * 32 + c];
        acc[c] = a;
    }
    float4* out = (float4*)(g_hA + (size_t)q * 32);
#pragma unroll
    for (int i = 0; i < 8; i++)
        out[i] = make_float4(acc[4 * i], acc[4 * i + 1], acc[4 * i + 2], acc[4 * i + 3]);
}

// ----------------- F1: y-DFT, channel-last input, block=(bv,x) -----------------
__global__ void __launch_bounds__(256) f1cl(int s_in) {
    __shared__ float sT[256 * 33];
    int tid = threadIdx.x;
    int bv = blockIdx.x >> 8, x = blockIdx.x & 255;
    const float4* in = (const float4*)(bufsel(s_in) + ((size_t)bv * 65536 + (size_t)x * 256) * 32);
#pragma unroll
    for (int i = 0; i < 8; i++) {
        int e = tid + i * 256;           // float4 index 0..2047
        float4 f = in[e];
        int y = e >> 3, c = (e & 7) * 4;
        sT[y * 33 + c]     = f.x;
        sT[y * 33 + c + 1] = f.y;
        sT[y * 33 + c + 2] = f.z;
        sT[y * 33 + c + 3] = f.w;
    }
    __syncthreads();
    // parity fold in place: sT[y]=e, sT[y+128]=o
#pragma unroll
    for (int i = 0; i < 16; i++) {
        int e = tid + i * 256;           // 0..4095: y<128, c
        int y = e >> 5, c = e & 31;
        float a = sT[y * 33 + c], b = sT[(y + 128) * 33 + c];
        sT[y * 33 + c] = a + b;
        sT[(y + 128) * 33 + c] = a - b;
    }
    __syncthreads();
    int c = tid >> 3, m0 = (tid & 7) * 4;
    const float* base = sT + ((m0 >= 16) ? 128 * 33 : 0);
    u64 a0 = 0ull, a1 = 0ull;
#pragma unroll 4
    for (int u = 0; u < 128; u++) {
        float h = base[u * 33 + c];
        u64 hh = pk2(h, h);
        longlong2 e2 = *(const longlong2*)&g_EfP[u * 32 + m0];
        a0 = fma2((u64)e2.x, hh, a0);
        a1 = fma2((u64)e2.y, hh, a1);
    }
    float l0, h0, l1, h1;
    upk2(a0, l0, h0); upk2(a1, l1, h1);
    *(float4*)&g_Y[(((size_t)bv * 32 + c) * 256 + x) * 32 + m0] = make_float4(l0, h0, l1, h1);
}

// ----------------- F2: x-DFT with x-parity fold (unchanged) -----------------
__global__ void __launch_bounds__(256) dftxF_t() {
    __shared__ float sYe[4096];
    __shared__ float sYo[4096];
    __shared__ float sO[64 * 33];
    int tid = threadIdx.x;
    int bvc = blockIdx.x;
    const float4* Yg = (const float4*)g_Y + (size_t)bvc * 2048;
#pragma unroll
    for (int i = 0; i < 4; i++) {
        int e = tid + i * 256;
        float4 a = Yg[e];
        float4 b = Yg[e + 1024];
        ((float4*)sYe)[e] = make_float4(a.x + b.x, a.y + b.y, a.z + b.z, a.w + b.w);
        ((float4*)sYo)[e] = make_float4(a.x - b.x, a.y - b.y, a.z - b.z, a.w - b.w);
    }
    __syncthreads();
    int m0 = (tid >> 3) * 2, c0 = (tid & 7) * 4;
    const float* sYp = (m0 < 32) ? sYe : sYo;
    u64 acc2[4] = {0ull, 0ull, 0ull, 0ull};
#pragma unroll 8
    for (int kk = 0; kk < 128; kk++) {
        u64 am = *(const u64*)&g_E2P[kk * 64 + m0];
        float4 yv = *(const float4*)&sYp[kk * 32 + c0];
        acc2[0] = fma2(am, pk2(yv.x, yv.x), acc2[0]);
        acc2[1] = fma2(am, pk2(yv.y, yv.y), acc2[1]);
        acc2[2] = fma2(am, pk2(yv.z, yv.z), acc2[2]);
        acc2[3] = fma2(am, pk2(yv.w, yv.w), acc2[3]);
    }
#pragma unroll
    for (int j = 0; j < 4; j++) {
        float lo, hi;
        upk2(acc2[j], lo, hi);
        sO[m0 * 33 + c0 + j] = lo;
        sO[(m0 + 1) * 33 + c0 + j] = hi;
    }
    __syncthreads();
    int c = bvc & 31, bv = bvc >> 5;
    int b = bv / 3, v = bv - 3 * b;
    float2* X1c = (float2*)g_X1;
#pragma unroll
    for (int t = tid; t < 512; t += 256) {
        int kx = t >> 4, ky = t & 15;
        int pe = (ky & 1) * 16 + (ky >> 1);
        int pi = pe + 8;
        int mc = (kx & 1) * 32 + (kx >> 1);
        int ms = mc + 16;
        float re = sO[mc * 33 + pe] + sO[ms * 33 + pi];
        float im = sO[mc * 33 + pi] - sO[ms * 33 + pe];
        X1c[(size_t)(v * 32 + kx) * 2048 + ky * 128 + b * 32 + c] = make_float2(re, im);
    }
}

// ----------------- MIX (unchanged) -----------------
__global__ void __launch_bounds__(256) mixmodes(const float* __restrict__ w1r,
                                                const float* __restrict__ w1i,
                                                const float* __restrict__ w2r,
                                                const float* __restrict__ w2i) {
    __shared__ float2 sXc[2048];
    __shared__ float sWr[2048], sWi[2048];
    int tid = threadIdx.x;
    int bx = blockIdx.x;
    int v = bx >> 8, kx = (bx >> 3) & 31, oc = bx & 7;
    int mx = (kx < 16) ? kx : (kx - 16);
    const float* wr = (kx < 16) ? w1r : w2r;
    const float* wi = (kx < 16) ? w1i : w2i;
    const float2* x1f2 = (const float2*)g_X1;
    for (int e = tid; e < 2048; e += 256) {
        int ky = e >> 7, b = (e >> 5) & 3, i = e & 31;
        sXc[i * 64 + ky * 4 + b] = x1f2[(size_t)(v * 32 + kx) * 2048 + e];
    }
    for (int e = tid; e < 2048; e += 256) {
        int i = e >> 6, oo = (e >> 4) & 3, my = e & 15;
        size_t src = (size_t)i * 24576 + (size_t)(oc * 4 + oo) * 768 + v * 256 + mx * 16 + my;
        sWr[e] = wr[src];
        sWi[e] = wi[src];
    }
    __syncthreads();
    int o_ = tid >> 6, ky = (tid >> 2) & 15, b = tid & 3;
    float zr = 0.f, zi = 0.f;
#pragma unroll
    for (int i = 0; i < 32; i++) {
        float wrv = sWr[i * 64 + o_ * 16 + ky];
        float wiv = sWi[i * 64 + o_ * 16 + ky];
        float2 xv = sXc[i * 64 + ky * 4 + b];
        zr += xv.x * wrv - xv.y * wiv;
        zi += xv.x * wiv + xv.y * wrv;
    }
    int og = oc * 4 + o_;
    int bvo = (b * 3 + v) * 32 + og;
    ((float2*)g_X2)[(bvo * 32 + kx) * 16 + ky] = make_float2(zr, zi);
}

// ----------------- I1: inverse x-DFT with x-parity fold (unchanged) -----------------
__global__ void __launch_bounds__(256) dftxI_t() {
    __shared__ float sGp[64 * 32];
    int tid = threadIdx.x;
    int bvo = blockIdx.x;
    const float2* F = (const float2*)g_X2 + (size_t)bvo * 512;
#pragma unroll
    for (int t = tid; t < 512; t += 256) {
        int kx = t >> 4, ky = t & 15;
        float2 f = F[t];
        int base = (kx & 1) * 32 + (kx >> 1) * 2;
        sGp[base * 32 + ky]            = f.x;
        sGp[base * 32 + 16 + ky]       = f.y;
        sGp[(base + 1) * 32 + ky]      = -f.y;
        sGp[(base + 1) * 32 + 16 + ky] = f.x;
    }
    __syncthreads();
    int x0 = (tid >> 3) * 4, c0 = (tid & 7) * 4;
    u64 accE[2][4], accO[2][4];
#pragma unroll
    for (int i = 0; i < 2; i++)
#pragma unroll
        for (int j = 0; j < 4; j++) { accE[i][j] = 0ull; accO[i][j] = 0ull; }
#pragma unroll 8
    for (int kk = 0; kk < 32; kk++) {
        longlong2 la = *(const longlong2*)&g_EIP[kk * 128 + x0];
        float4 d = *(const float4*)&sGp[kk * 32 + c0];
        u64 a0 = (u64)la.x, a1 = (u64)la.y;
        u64 db[4] = {pk2(d.x, d.x), pk2(d.y, d.y), pk2(d.z, d.z), pk2(d.w, d.w)};
#pragma unroll
        for (int j = 0; j < 4; j++) {
            accE[0][j] = fma2(a0, db[j], accE[0][j]);
            accE[1][j] = fma2(a1, db[j], accE[1][j]);
        }
    }
#pragma unroll 8
    for (int kk = 32; kk < 64; kk++) {
        longlong2 la = *(const longlong2*)&g_EIP[kk * 128 + x0];
        float4 d = *(const float4*)&sGp[kk * 32 + c0];
        u64 a0 = (u64)la.x, a1 = (u64)la.y;
        u64 db[4] = {pk2(d.x, d.x), pk2(d.y, d.y), pk2(d.z, d.z), pk2(d.w, d.w)};
#pragma unroll
        for (int j = 0; j < 4; j++) {
            accO[0][j] = fma2(a0, db[j], accO[0][j]);
            accO[1][j] = fma2(a1, db[j], accO[1][j]);
        }
    }
#pragma unroll
    for (int i = 0; i < 2; i++) {
        float el[4], eh[4], ol[4], oh[4];
#pragma unroll
        for (int j = 0; j < 4; j++) {
            upk2(accE[i][j], el[j], eh[j]);
            upk2(accO[i][j], ol[j], oh[j]);
        }
        size_t row0 = (size_t)bvo * 256 + x0 + 2 * i;
        *(float4*)&g_Z[row0 * 32 + c0] =
            make_float4(el[0] + ol[0], el[1] + ol[1], el[2] + ol[2], el[3] + ol[3]);
        *(float4*)&g_Z[(row0 + 128) * 32 + c0] =
            make_float4(el[0] - ol[0], el[1] - ol[1], el[2] - ol[2], el[3] - ol[3]);
        *(float4*)&g_Z[(row0 + 1) * 32 + c0] =
            make_float4(eh[0] + oh[0], eh[1] + oh[1], eh[2] + oh[2], eh[3] + oh[3]);
        *(float4*)&g_Z[(row0 + 129) * 32 + c0] =
            make_float4(eh[0] - oh[0], eh[1] - oh[1], eh[2] - oh[2], eh[3] - oh[3]);
    }
}

// ----------------- I2: inverse y-DFT, channel-last out, block=(bv,x), thread=y -----------------
__global__ void __launch_bounds__(256) idftycl() {
    __shared__ float sZT[32 * 36];   // [j][c], 16B-aligned rows
    int tid = threadIdx.x;
    int bv = blockIdx.x >> 8, x = blockIdx.x & 255;
    {
        int c = tid >> 3, jq = tid & 7;
        float4 f = *(const float4*)&g_Z[(((size_t)bv * 32 + c) * 256 + x) * 32 + jq * 4];
        sZT[(jq * 4 + 0) * 36 + c] = f.x;
        sZT[(jq * 4 + 1) * 36 + c] = f.y;
        sZT[(jq * 4 + 2) * 36 + c] = f.z;
        sZT[(jq * 4 + 3) * 36 + c] = f.w;
    }
    __syncthreads();
    int y = tid;
    u64 acc2[16];
#pragma unroll
    for (int c = 0; c < 16; c++) acc2[c] = 0ull;
#pragma unroll 4
    for (int j = 0; j < 32; j++) {
        float dy = __ldg(&g_Dy[j * 256 + y]);
        u64 dd = pk2(dy, dy);
        const longlong2* zr = (const longlong2*)&sZT[j * 36];
#pragma unroll
        for (int q = 0; q < 8; q++) {
            longlong2 zv = zr[q];
            acc2[2 * q]     = fma2((u64)zv.x, dd, acc2[2 * q]);
            acc2[2 * q + 1] = fma2((u64)zv.y, dd, acc2[2 * q + 1]);
        }
    }
    float4* out = (float4*)(g_spec + ((size_t)bv * 65536 + (size_t)x * 256 + y) * 32);
#pragma unroll
    for (int q = 0; q < 8; q++) {
        float f0, f1, f2, f3;
        upk2(acc2[2 * q], f0, f1);
        upk2(acc2[2 * q + 1], f2, f3);
        out[q] = make_float4(f0, f1, f2, f3);
    }
}

// ----------------- fused pointwise chain (channel-last I/O) -----------------
__global__ void __launch_bounds__(256) convfuse(int s_t, int s_res, int s_out,
        const float* __restrict__ m1w, const float* __restrict__ m1b,
        const float* __restrict__ m2w, const float* __restrict__ m2b,
        const float* __restrict__ ww,  const float* __restrict__ wb,
        const float* __restrict__ bw,  const float* __restrict__ bb) {
    __shared__ float sM1[1024], sM2T[1024], sWW[1024];
    __shared__ float sB1[32], sB0[32], sBX[32], sBY[32];
    int tid = threadIdx.x;
    for (int e = tid; e < 1024; e += 256) {
        sM1[e] = m1w[e];
        sWW[e] = ww[e];
        sM2T[(e & 31) * 32 + (e >> 5)] = m2w[e];
    }
    if (tid < 32) {
        sB1[tid] = m1b[tid];
        sB0[tid] = m2b[tid] + wb[tid] + bb[tid];
        sBX[tid] = bw[tid * 2];
        sBY[tid] = bw[tid * 2 + 1];
    }
    __syncthreads();
    int q = blockIdx.x * 256 + tid;
    int p = q & 65535;
    float gx = (float)(p >> 8) * (1.0f / 255.0f);
    float gy = (float)(p & 255) * (1.0f / 255.0f);
    size_t base = (size_t)q * 32;
    const longlong2* tq = (const longlong2*)(bufsel(s_t) + base);
    u64 ap[16];
#pragma unroll
    for (int q2 = 0; q2 < 8; q2++) {
        longlong2 v = tq[q2];
        ap[2 * q2] = (u64)v.x;
        ap[2 * q2 + 1] = (u64)v.y;
    }
    u64 acc2[16];
#pragma unroll
    for (int oq = 0; oq < 16; oq++) {
        float rr0, rr1;
#pragma unroll
        for (int h = 0; h < 2; h++) {
            int o = 2 * oq + h;
            u64 sa = pk2(sB0[o] + sBX[o] * gx + sBY[o] * gy, 0.f);
            u64 sb = 0ull;
            const longlong2* wp = (const longlong2*)&sWW[o * 32];
#pragma unroll
            for (int q2 = 0; q2 < 8; q2++) {
                longlong2 wv = wp[q2];
                sa = fma2((u64)wv.x, ap[2 * q2], sa);
                sb = fma2((u64)wv.y, ap[2 * q2 + 1], sb);
            }
            float l0, h0, l1, h1;
            upk2(sa, l0, h0); upk2(sb, l1, h1);
            float r = (l0 + h0) + (l1 + h1);
            if (h == 0) rr0 = r; else rr1 = r;
        }
        acc2[oq] = pk2(rr0, rr1);
    }
    const longlong2* sq = (const longlong2*)(g_spec + base);
#pragma unroll
    for (int q2 = 0; q2 < 8; q2++) {
        longlong2 v = sq[q2];
        ap[2 * q2] = (u64)v.x;
        ap[2 * q2 + 1] = (u64)v.y;
    }
#pragma unroll
    for (int o = 0; o < 32; o++) {
        u64 sa = pk2(sB1[o], 0.f);
        u64 sb = 0ull;
        const longlong2* wp = (const longlong2*)&sM1[o * 32];
#pragma unroll
        for (int q2 = 0; q2 < 8; q2++) {
            longlong2 wv = wp[q2];
            sa = fma2((u64)wv.x, ap[2 * q2], sa);
            sb = fma2((u64)wv.y, ap[2 * q2 + 1], sb);
        }
        float l0, h0, l1, h1;
        upk2(sa, l0, h0); upk2(sb, l1, h1);
        float g = gelu_f((l0 + h0) + (l1 + h1));
        u64 gg = pk2(g, g);
        const longlong2* mp = (const longlong2*)&sM2T[o * 32];
#pragma unroll
        for (int q2 = 0; q2 < 8; q2++) {
            longlong2 mv = mp[q2];
            acc2[2 * q2]     = fma2((u64)mv.x, gg, acc2[2 * q2]);
            acc2[2 * q2 + 1] = fma2((u64)mv.y, gg, acc2[2 * q2 + 1]);
        }
    }
    float4* op = (float4*)(bufsel(s_out) + base);
    const float4* rp = (s_res >= 0) ? (const float4*)(bufsel(s_res) + base) : (const float4*)0;
#pragma unroll
    for (int q2 = 0; q2 < 8; q2++) {
        float f0, f1, f2, f3;
        upk2(acc2[2 * q2], f0, f1);
        upk2(acc2[2 * q2 + 1], f2, f3);
        float4 v = make_float4(gelu_f(f0), gelu_f(f1), gelu_f(f2), gelu_f(f3));
        if (rp) {
            float4 r = rp[q2];
            v.x += r.x; v.y += r.y; v.z += r.z; v.w += r.w;
        }
        op[q2] = v;
    }
}

// ----------------- head: fused fc1v + fc1t + gelu + fc2t (channel-last in) -----------------
__global__ void __launch_bounds__(256) head_kernel(const float* __restrict__ vw,
                                                   const float* __restrict__ vb,
                                                   const float* __restrict__ b1,
                                                   const float* __restrict__ w2,
                                                   const float* __restrict__ b2,
                                                   float* __restrict__ dout) {
    __shared__ float sW1T[8192];
    __shared__ float sW2[2560];
    __shared__ float sB1h[256];
    int tid = threadIdx.x;
    for (int e = tid; e < 8192; e += 256) sW1T[e] = g_W1T[e];
    for (int e = tid; e < 2560; e += 256) sW2[e] = w2[e];
    sB1h[tid] = b1[tid];
    __syncthreads();
    int q = blockIdx.x * 256 + tid;
    int bvo = q >> 16, p = q & 65535;
    int b = bvo / 3, vo = bvo - 3 * b;
    float w0 = __ldg(&vw[vo]), w1 = __ldg(&vw[3 + vo]), w2v = __ldg(&vw[6 + vo]);
    float vbias = __ldg(&vb[vo]);
    const float4* h0 = (const float4*)(g_hA + ((size_t)(b * 3 + 0) * 65536 + p) * 32);
    const float4* h1 = (const float4*)(g_hA + ((size_t)(b * 3 + 1) * 65536 + p) * 32);
    const float4* h2 = (const float4*)(g_hA + ((size_t)(b * 3 + 2) * 65536 + p) * 32);
    u64 ap[16];
#pragma unroll
    for (int i = 0; i < 8; i++) {
        float4 a = h0[i], c = h1[i], d = h2[i];
        float t0 = a.x * w0 + c.x * w1 + d.x * w2v + vbias;
        float t1 = a.y * w0 + c.y * w1 + d.y * w2v + vbias;
        float t2 = a.z * w0 + c.z * w1 + d.z * w2v + vbias;
        float t3 = a.w * w0 + c.w * w1 + d.w * w2v + vbias;
        ap[2 * i]     = pk2(gelu_f(t0), gelu_f(t1));
        ap[2 * i + 1] = pk2(gelu_f(t2), gelu_f(t3));
    }
    u64 o2[5];
#pragma unroll
    for (int s = 0; s < 5; s++) o2[s] = pk2(__ldg(&b2[2 * s]), __ldg(&b2[2 * s + 1]));
    for (int j = 0; j < 256; j++) {
        u64 ua = pk2(sB1h[j], 0.f);
        u64 ub = 0ull;
        const longlong2* wp = (const longlong2*)&sW1T[j * 32];
#pragma unroll
        for (int q2 = 0; q2 < 8; q2++) {
            longlong2 wv = wp[q2];
            ua = fma2((u64)wv.x, ap[2 * q2], ua);
            ub = fma2((u64)wv.y, ap[2 * q2 + 1], ub);
        }
        float l0, h0v, l1, h1v;
        upk2(ua, l0, h0v); upk2(ub, l1, h1v);
        float g = gelu_f((l0 + h0v) + (l1 + h1v));
        u64 gg = pk2(g, g);
        const u64* w2p = (const u64*)&sW2[j * 10];
#pragma unroll
        for (int s = 0; s < 5; s++) o2[s] = fma2(w2p[s], gg, o2[s]);
    }
    float2* op = (float2*)(dout + (size_t)bvo * 655360 + (size_t)p * 10);
#pragma unroll
    for (int s = 0; s < 5; s++) {
        float lo, hi;
        upk2(o2[s], lo, hi);
        op[s] = make_float2(lo, hi);
    }
}

// ----------------- launch -----------------
extern "C" void kernel_launch(void* const* d_in, const int* in_sizes, int n_in,
                              void* d_out, int out_size) {
    const float* x      = (const float*)d_in[0];
    const float* fc0_w  = (const float*)d_in[1];
    const float* fc0_b  = (const float*)d_in[2];
    const float* w1r    = (const float*)d_in[3];
    const float* w1i    = (const float*)d_in[4];
    const float* w2r    = (const float*)d_in[5];
    const float* w2i    = (const float*)d_in[6];
    const float* m1w    = (const float*)d_in[7];
    const float* m1b    = (const float*)d_in[8];
    const float* m2w    = (const float*)d_in[9];
    const float* m2b    = (const float*)d_in[10];
    const float* ww     = (const float*)d_in[11];
    const float* wb     = (const float*)d_in[12];
    const float* bw     = (const float*)d_in[13];
    const float* bb     = (const float*)d_in[14];
    const float* fc1v_w = (const float*)d_in[15];
    const float* fc1v_b = (const float*)d_in[16];
    const float* fc1t_w = (const float*)d_in[17];
    const float* fc1t_b = (const float*)d_in[18];
    const float* fc2t_w = (const float*)d_in[19];
    const float* fc2t_b = (const float*)d_in[20];
    float* out = (float*)d_out;

    setup_basis<<<48, 256>>>();
    setup_perm<<<16, 256>>>();
    transposeW1<<<32, 256>>>(fc1t_w);
    fc0_kernel<<<3072, 256>>>(x, fc0_w, fc0_b);

    const int tin[6]  = {0, 1, 2, 0, 1, 2};
    const int tout[6] = {1, 2, 0, 1, 2, 0};
    const int tres[6] = {-1, -1, 1, -1, -1, 1};
    for (int l = 0; l < 6; l++) {
        f1cl<<<3072, 256>>>(tin[l]);
        dftxF_t<<<384, 256>>>();
        mixmodes<<<768, 256>>>(w1r + (size_t)l * 786432, w1i + (size_t)l * 786432,
                               w2r + (size_t)l * 786432, w2i + (size_t)l * 786432);
        dftxI_t<<<384, 256>>>();
        idftycl<<<3072, 256>>>();
        convfuse<<<3072, 256>>>(tin[l], tres[l], tout[l],
                                m1w + l * 1024, m1b + l * 32,
                                m2w + l * 1024, m2b + l * 32,
                                ww + l * 1024,  wb + l * 32,
                                bw + l * 64,    bb + l * 32);
    }
    head_kernel<<<3072, 256>>>(fc1v_w, fc1v_b, fc1t_b, fc2t_w, fc2t_b, out);
}

// round 12
// speedup vs baseline: 1.2023x; 1.2023x over previous
#include <cuda_runtime.h>
#include <math.h>

#define HBUF 25165824   // 12*32*65536 floats, channel-major [bv][c][p]

__device__ float g_hA[HBUF];
__device__ float g_hB[HBUF];
__device__ float g_hC[HBUF];
__device__ float g_Y[3145728];    // [row=bvc*256+x][32]  parity-permuted cols
__device__ float g_Z[3145728];    // [row=bvo*256+x][32]  (16 gr | 16 gi)
__device__ float g_X1[393216];
__device__ float g_X2[393216];
__device__ float g_Ef[8192];      // [y][32]: k<16 cos, k>=16 -sin
__device__ float g_Dy[8192];      // [j32][y] inverse-y real basis
__device__ float g_E2P[8192];     // [x128][m64] parity-permuted fwd-x basis
__device__ float g_EIP[8192];     // [kk64][x128] parity-permuted inv-x basis /256
__device__ float g_W1T[8192];     // fc1t_w transposed [j256][c32]

typedef unsigned long long u64;

__device__ __forceinline__ u64 pk2(float lo, float hi) {
    u64 r; asm("mov.b64 %0,{%1,%2};" : "=l"(r) : "f"(lo), "f"(hi)); return r;
}
__device__ __forceinline__ void upk2(u64 v, float& lo, float& hi) {
    asm("mov.b64 {%0,%1},%2;" : "=f"(lo), "=f"(hi) : "l"(v));
}
__device__ __forceinline__ u64 fma2(u64 a, u64 b, u64 c) {
    u64 d; asm("fma.rn.f32x2 %0,%1,%2,%3;" : "=l"(d) : "l"(a), "l"(b), "l"(c)); return d;
}
__device__ __forceinline__ float gelu_f(float x) {
    return 0.5f * x * (1.0f + erff(x * 0.70710678118654752440f));
}
__device__ __forceinline__ float* bufsel(int s) {
    if (s == 0) return g_hA;
    if (s == 1) return g_hB;
    return g_hC;
}

// ----------------- basis tables -----------------
__global__ void setup_basis() {
    int x = threadIdx.x;
    int t = blockIdx.x;
    if (t < 16) {
        int k = t;
        double sv, cv;
        sincospi(((double)(k * x)) / 128.0, &sv, &cv);
        g_Ef[x * 32 + k]      = (float)cv;
        g_Ef[x * 32 + 16 + k] = (float)(-sv);
        double cj = (k == 0) ? 1.0 : 2.0;
        g_Dy[k * 256 + x]        = (float)( cj * cv / 256.0);
        g_Dy[(16 + k) * 256 + x] = (float)(-cj * sv / 256.0);
    } else {
        int j = t - 16;
        int f = (j < 16) ? j : (224 + j);
        double sv, cv;
        sincospi(((double)(f * x)) / 128.0, &sv, &cv);
        if (x < 128) {
            int p = j & 1, jh = j >> 1;
            g_E2P[x * 64 + p * 32 + jh]      = (float)cv;
            g_E2P[x * 64 + p * 32 + 16 + jh] = (float)sv;
            int base = p * 32 + jh * 2;
            g_EIP[base * 128 + x]       = (float)(cv / 256.0);
            g_EIP[(base + 1) * 128 + x] = (float)(sv / 256.0);
        }
    }
}

__global__ void transposeW1(const float* __restrict__ w) {
    int t = blockIdx.x * 256 + threadIdx.x;
    int c = t >> 8, j = t & 255;
    g_W1T[j * 32 + c] = w[t];
}

// ----------------- fc0 lift (channel-major out) -----------------
__global__ void __launch_bounds__(256) fc0_kernel(const float* __restrict__ xin,
                                                  const float* __restrict__ w,
                                                  const float* __restrict__ b) {
    __shared__ float sW[384];
    __shared__ float sB[32];
    int tid = threadIdx.x;
    for (int i = tid; i < 384; i += 256) sW[i] = w[i];
    if (tid < 32) sB[tid] = b[tid];
    __syncthreads();
    int q = blockIdx.x * 256 + tid;
    int bv = q >> 16, p = q & 65535;
    float xv[12];
    const float* xp = xin + (size_t)q * 10;
#pragma unroll
    for (int t = 0; t < 10; t++) xv[t] = xp[t];
    xv[10] = (float)(p >> 8) * (1.0f / 255.0f);
    xv[11] = (float)(p & 255) * (1.0f / 255.0f);
    float* out = g_hA + (size_t)bv * 2097152 + p;
#pragma unroll
    for (int c = 0; c < 32; c++) {
        float acc = sB[c];
#pragma unroll
        for (int t = 0; t < 12; t++) acc += xv[t] * sW[t * 32 + c];
        out[(size_t)c * 65536] = acc;
    }
}

// ----------------- F1: y-DFT with parity fold (y <-> y+128), K=128 -----------------
__global__ void __launch_bounds__(256) gemmF1_t(int s_in) {
    const float* __restrict__ A = bufsel(s_in);
    __shared__ float sAe[32 * 132];
    __shared__ float sAo[32 * 132];
    __shared__ float sEp[32 * 36];
    int tid = threadIdx.x;
    size_t rb = (size_t)blockIdx.x * 128;
    int r0 = (tid >> 3) * 4, c0 = (tid & 7) * 4;
    int lr = tid >> 1, lh = tid & 1;
    const float* sA = ((tid & 7) < 4) ? sAe : sAo;
    u64 acc2[2][4];
#pragma unroll
    for (int i = 0; i < 2; i++)
#pragma unroll
        for (int j = 0; j < 4; j++) acc2[i][j] = 0ull;

    for (int kt = 0; kt < 4; kt++) {
        __syncthreads();
        const float* Arow = A + (rb + lr) * 256 + kt * 32 + lh * 16;
#pragma unroll
        for (int i = 0; i < 4; i++) {
            float4 fa = *(const float4*)(Arow + i * 4);
            float4 fb = *(const float4*)(Arow + 128 + i * 4);
            int yy = lh * 16 + i * 4;
            sAe[(yy + 0) * 132 + lr] = fa.x + fb.x;
            sAo[(yy + 0) * 132 + lr] = fa.x - fb.x;
            sAe[(yy + 1) * 132 + lr] = fa.y + fb.y;
            sAo[(yy + 1) * 132 + lr] = fa.y - fb.y;
            sAe[(yy + 2) * 132 + lr] = fa.z + fb.z;
            sAo[(yy + 2) * 132 + lr] = fa.z - fb.z;
            sAe[(yy + 3) * 132 + lr] = fa.w + fb.w;
            sAo[(yy + 3) * 132 + lr] = fa.w - fb.w;
        }
#pragma unroll
        for (int i = 0; i < 4; i++) {
            int e = tid + i * 256;
            int u = e >> 5, m = e & 31;
            int col = ((m >> 3) & 1) * 16 + 2 * (m & 7) + (m >> 4);
            sEp[u * 36 + m] = g_Ef[(kt * 32 + u) * 32 + col];
        }
        __syncthreads();
#pragma unroll
        for (int kk = 0; kk < 32; kk++) {
            longlong2 la = *(const longlong2*)&sA[kk * 132 + r0];
            float4 e4 = *(const float4*)&sEp[kk * 36 + c0];
            u64 a0 = (u64)la.x, a1 = (u64)la.y;
            u64 eb[4] = {pk2(e4.x, e4.x), pk2(e4.y, e4.y), pk2(e4.z, e4.z), pk2(e4.w, e4.w)};
#pragma unroll
            for (int j = 0; j < 4; j++) {
                acc2[0][j] = fma2(a0, eb[j], acc2[0][j]);
                acc2[1][j] = fma2(a1, eb[j], acc2[1][j]);
            }
        }
    }
#pragma unroll
    for (int i = 0; i < 2; i++) {
        float lo0, hi0, lo1, hi1, lo2, hi2, lo3, hi3;
        upk2(acc2[i][0], lo0, hi0); upk2(acc2[i][1], lo1, hi1);
        upk2(acc2[i][2], lo2, hi2); upk2(acc2[i][3], lo3, hi3);
        *(float4*)&g_Y[(rb + r0 + 2 * i) * 32 + c0]     = make_float4(lo0, lo1, lo2, lo3);
        *(float4*)&g_Y[(rb + r0 + 2 * i + 1) * 32 + c0] = make_float4(hi0, hi1, hi2, hi3);
    }
}

// ----------------- F2: x-DFT with x-parity fold -----------------
__global__ void __launch_bounds__(256) dftxF_t() {
    __shared__ float sYe[4096];
    __shared__ float sYo[4096];
    __shared__ float sO[64 * 33];
    int tid = threadIdx.x;
    int bvc = blockIdx.x;
    const float4* Yg = (const float4*)g_Y + (size_t)bvc * 2048;
#pragma unroll
    for (int i = 0; i < 4; i++) {
        int e = tid + i * 256;
        float4 a = Yg[e];
        float4 b = Yg[e + 1024];
        ((float4*)sYe)[e] = make_float4(a.x + b.x, a.y + b.y, a.z + b.z, a.w + b.w);
        ((float4*)sYo)[e] = make_float4(a.x - b.x, a.y - b.y, a.z - b.z, a.w - b.w);
    }
    __syncthreads();
    int m0 = (tid >> 3) * 2, c0 = (tid & 7) * 4;
    const float* sYp = (m0 < 32) ? sYe : sYo;
    u64 acc2[4] = {0ull, 0ull, 0ull, 0ull};
#pragma unroll 8
    for (int kk = 0; kk < 128; kk++) {
        u64 am = *(const u64*)&g_E2P[kk * 64 + m0];
        float4 yv = *(const float4*)&sYp[kk * 32 + c0];
        acc2[0] = fma2(am, pk2(yv.x, yv.x), acc2[0]);
        acc2[1] = fma2(am, pk2(yv.y, yv.y), acc2[1]);
        acc2[2] = fma2(am, pk2(yv.z, yv.z), acc2[2]);
        acc2[3] = fma2(am, pk2(yv.w, yv.w), acc2[3]);
    }
#pragma unroll
    for (int j = 0; j < 4; j++) {
        float lo, hi;
        upk2(acc2[j], lo, hi);
        sO[m0 * 33 + c0 + j] = lo;
        sO[(m0 + 1) * 33 + c0 + j] = hi;
    }
    __syncthreads();
    int c = bvc & 31, bv = bvc >> 5;
    int b = bv / 3, v = bv - 3 * b;
    float2* X1c = (float2*)g_X1;
#pragma unroll
    for (int t = tid; t < 512; t += 256) {
        int kx = t >> 4, ky = t & 15;
        int pe = (ky & 1) * 16 + (ky >> 1);
        int pi = pe + 8;
        int mc = (kx & 1) * 32 + (kx >> 1);
        int ms = mc + 16;
        float re = sO[mc * 33 + pe] + sO[ms * 33 + pi];
        float im = sO[mc * 33 + pi] - sO[ms * 33 + pe];
        X1c[(size_t)(v * 32 + kx) * 2048 + ky * 128 + b * 32 + c] = make_float2(re, im);
    }
}

// ----------------- MIX -----------------
__global__ void __launch_bounds__(256) mixmodes(const float* __restrict__ w1r,
                                                const float* __restrict__ w1i,
                                                const float* __restrict__ w2r,
                                                const float* __restrict__ w2i) {
    __shared__ float2 sXc[2048];
    __shared__ float sWr[2048], sWi[2048];
    int tid = threadIdx.x;
    int bx = blockIdx.x;
    int v = bx >> 8, kx = (bx >> 3) & 31, oc = bx & 7;
    int mx = (kx < 16) ? kx : (kx - 16);
    const float* wr = (kx < 16) ? w1r : w2r;
    const float* wi = (kx < 16) ? w1i : w2i;
    const float2* x1f2 = (const float2*)g_X1;
    for (int e = tid; e < 2048; e += 256) {
        int ky = e >> 7, b = (e >> 5) & 3, i = e & 31;
        sXc[i * 64 + ky * 4 + b] = x1f2[(size_t)(v * 32 + kx) * 2048 + e];
    }
    for (int e = tid; e < 2048; e += 256) {
        int i = e >> 6, oo = (e >> 4) & 3, my = e & 15;
        size_t src = (size_t)i * 24576 + (size_t)(oc * 4 + oo) * 768 + v * 256 + mx * 16 + my;
        sWr[e] = wr[src];
        sWi[e] = wi[src];
    }
    __syncthreads();
    int o_ = tid >> 6, ky = (tid >> 2) & 15, b = tid & 3;
    float zr = 0.f, zi = 0.f;
#pragma unroll
    for (int i = 0; i < 32; i++) {
        float wrv = sWr[i * 64 + o_ * 16 + ky];
        float wiv = sWi[i * 64 + o_ * 16 + ky];
        float2 xv = sXc[i * 64 + ky * 4 + b];
        zr += xv.x * wrv - xv.y * wiv;
        zi += xv.x * wiv + xv.y * wrv;
    }
    int og = oc * 4 + o_;
    int bvo = (b * 3 + v) * 32 + og;
    ((float2*)g_X2)[(bvo * 32 + kx) * 16 + ky] = make_float2(zr, zi);
}

// ----------------- I1: inverse x-DFT with x-parity fold -----------------
__global__ void __launch_bounds__(256) dftxI_t() {
    __shared__ float sGp[64 * 32];
    int tid = threadIdx.x;
    int bvo = blockIdx.x;
    const float2* F = (const float2*)g_X2 + (size_t)bvo * 512;
#pragma unroll
    for (int t = tid; t < 512; t += 256) {
        int kx = t >> 4, ky = t & 15;
        float2 f = F[t];
        int base = (kx & 1) * 32 + (kx >> 1) * 2;
        sGp[base * 32 + ky]            = f.x;
        sGp[base * 32 + 16 + ky]       = f.y;
        sGp[(base + 1) * 32 + ky]      = -f.y;
        sGp[(base + 1) * 32 + 16 + ky] = f.x;
    }
    __syncthreads();
    int x0 = (tid >> 3) * 4, c0 = (tid & 7) * 4;
    u64 accE[2][4], accO[2][4];
#pragma unroll
    for (int i = 0; i < 2; i++)
#pragma unroll
        for (int j = 0; j < 4; j++) { accE[i][j] = 0ull; accO[i][j] = 0ull; }
#pragma unroll 8
    for (int kk = 0; kk < 32; kk++) {
        longlong2 la = *(const longlong2*)&g_EIP[kk * 128 + x0];
        float4 d = *(const float4*)&sGp[kk * 32 + c0];
        u64 a0 = (u64)la.x, a1 = (u64)la.y;
        u64 db[4] = {pk2(d.x, d.x), pk2(d.y, d.y), pk2(d.z, d.z), pk2(d.w, d.w)};
#pragma unroll
        for (int j = 0; j < 4; j++) {
            accE[0][j] = fma2(a0, db[j], accE[0][j]);
            accE[1][j] = fma2(a1, db[j], accE[1][j]);
        }
    }
#pragma unroll 8
    for (int kk = 32; kk < 64; kk++) {
        longlong2 la = *(const longlong2*)&g_EIP[kk * 128 + x0];
        float4 d = *(const float4*)&sGp[kk * 32 + c0];
        u64 a0 = (u64)la.x, a1 = (u64)la.y;
        u64 db[4] = {pk2(d.x, d.x), pk2(d.y, d.y), pk2(d.z, d.z), pk2(d.w, d.w)};
#pragma unroll
        for (int j = 0; j < 4; j++) {
            accO[0][j] = fma2(a0, db[j], accO[0][j]);
            accO[1][j] = fma2(a1, db[j], accO[1][j]);
        }
    }
#pragma unroll
    for (int i = 0; i < 2; i++) {
        float el[4], eh[4], ol[4], oh[4];
#pragma unroll
        for (int j = 0; j < 4; j++) {
            upk2(accE[i][j], el[j], eh[j]);
            upk2(accO[i][j], ol[j], oh[j]);
        }
        size_t row0 = (size_t)bvo * 256 + x0 + 2 * i;
        *(float4*)&g_Z[row0 * 32 + c0] =
            make_float4(el[0] + ol[0], el[1] + ol[1], el[2] + ol[2], el[3] + ol[3]);
        *(float4*)&g_Z[(row0 + 128) * 32 + c0] =
            make_float4(el[0] - ol[0], el[1] - ol[1], el[2] - ol[2], el[3] - ol[3]);
        *(float4*)&g_Z[(row0 + 1) * 32 + c0] =
            make_float4(eh[0] + oh[0], eh[1] + oh[1], eh[2] + oh[2], eh[3] + oh[3]);
        *(float4*)&g_Z[(row0 + 129) * 32 + c0] =
            make_float4(eh[0] - oh[0], eh[1] - oh[1], eh[2] - oh[2], eh[3] - oh[3]);
    }
}

// ----------------- CONVSPEC: inline inverse-y DFT + fused pointwise chain -----------------
// block = (bv, x), thread = y. Phases keep <=2 packed arrays live.
__global__ void __launch_bounds__(256) convspec(int s_t, int s_res, int s_out,
        const float* __restrict__ m1w, const float* __restrict__ m1b,
        const float* __restrict__ m2w, const float* __restrict__ m2b,
        const float* __restrict__ ww,  const float* __restrict__ wb,
        const float* __restrict__ bw,  const float* __restrict__ bb) {
    __shared__ float sM1[1024], sM2T[1024], sWW[1024];
    __shared__ float sB1[32], sB0[32], sBX[32], sBY[32];
    __shared__ float sZT[1152];      // [j][c], pad 36
    int tid = threadIdx.x;
    int bv = blockIdx.x >> 8, x = blockIdx.x & 255, y = tid;
    for (int e = tid; e < 1024; e += 256) {
        sM1[e] = m1w[e];
        sWW[e] = ww[e];
        sM2T[(e & 31) * 32 + (e >> 5)] = m2w[e];
    }
    if (tid < 32) {
        sB1[tid] = m1b[tid];
        sB0[tid] = m2b[tid] + wb[tid] + bb[tid];
        sBX[tid] = bw[tid * 2];
        sBY[tid] = bw[tid * 2 + 1];
    }
#pragma unroll
    for (int i = 0; i < 4; i++) {
        int idx = tid + i * 256;
        int c = idx >> 5, j = idx & 31;
        sZT[j * 36 + c] = g_Z[(((size_t)bv * 32 + c) * 256 + x) * 32 + j];
    }
    __syncthreads();

    int p = (x << 8) | y;
    size_t base = (size_t)bv * 2097152 + p;
    float gx = (float)x * (1.0f / 255.0f);
    float gy = (float)y * (1.0f / 255.0f);

    // ---- phase 1: ap <- t (channel-major, coalesced); acc2 = ww.t + bias + bw.grid ----
    const float* tp = bufsel(s_t) + base;
    u64 ap[16];
#pragma unroll
    for (int c = 0; c < 16; c++)
        ap[c] = pk2(tp[(size_t)(2 * c) * 65536], tp[(size_t)(2 * c + 1) * 65536]);
    u64 acc2[16];
#pragma unroll
    for (int oq = 0; oq < 16; oq++) {
        float rr0, rr1;
#pragma unroll
        for (int h = 0; h < 2; h++) {
            int o = 2 * oq + h;
            u64 sa = pk2(sB0[o] + sBX[o] * gx + sBY[o] * gy, 0.f);
            u64 sb = 0ull;
            const longlong2* wp = (const longlong2*)&sWW[o * 32];
#pragma unroll
            for (int q2 = 0; q2 < 8; q2++) {
                longlong2 wv = wp[q2];
                sa = fma2((u64)wv.x, ap[2 * q2], sa);
                sb = fma2((u64)wv.y, ap[2 * q2 + 1], sb);
            }
            float l0, h0, l1, h1;
            upk2(sa, l0, h0); upk2(sb, l1, h1);
            float r = (l0 + h0) + (l1 + h1);
            if (h == 0) rr0 = r; else rr1 = r;
        }
        acc2[oq] = pk2(rr0, rr1);
    }

    // ---- phase 2: spk (inline inverse-y DFT from smem Z tile); ap is dead ----
    u64 spk[16];
#pragma unroll
    for (int c = 0; c < 16; c++) spk[c] = 0ull;
#pragma unroll 4
    for (int j = 0; j < 32; j++) {
        float dy = __ldg(&g_Dy[j * 256 + y]);
        u64 dd = pk2(dy, dy);
        const longlong2* zr = (const longlong2*)&sZT[j * 36];
#pragma unroll
        for (int q = 0; q < 8; q++) {
            longlong2 z2 = zr[q];
            spk[2 * q]     = fma2((u64)z2.x, dd, spk[2 * q]);
            spk[2 * q + 1] = fma2((u64)z2.y, dd, spk[2 * q + 1]);
        }
    }

    // ---- phase 3: acc2 += m2 . gelu(m1 . spk + b1) ----
#pragma unroll
    for (int o = 0; o < 32; o++) {
        u64 sa = pk2(sB1[o], 0.f);
        u64 sb = 0ull;
        const longlong2* wp = (const longlong2*)&sM1[o * 32];
#pragma unroll
        for (int q2 = 0; q2 < 8; q2++) {
            longlong2 wv = wp[q2];
            sa = fma2((u64)wv.x, spk[2 * q2], sa);
            sb = fma2((u64)wv.y, spk[2 * q2 + 1], sb);
        }
        float l0, h0, l1, h1;
        upk2(sa, l0, h0); upk2(sb, l1, h1);
        float g = gelu_f((l0 + h0) + (l1 + h1));
        u64 gg = pk2(g, g);
        const longlong2* mp = (const longlong2*)&sM2T[o * 32];
#pragma unroll
        for (int q2 = 0; q2 < 8; q2++) {
            longlong2 mv = mp[q2];
            acc2[2 * q2]     = fma2((u64)mv.x, gg, acc2[2 * q2]);
            acc2[2 * q2 + 1] = fma2((u64)mv.y, gg, acc2[2 * q2 + 1]);
        }
    }

    // ---- output: gelu + residual ----
    float* op = bufsel(s_out) + base;
    const float* rp = (s_res >= 0) ? (bufsel(s_res) + base) : (const float*)0;
#pragma unroll
    for (int c = 0; c < 16; c++) {
        float lo, hi;
        upk2(acc2[c], lo, hi);
        float v0 = gelu_f(lo), v1 = gelu_f(hi);
        if (rp) {
            v0 += rp[(size_t)(2 * c) * 65536];
            v1 += rp[(size_t)(2 * c + 1) * 65536];
        }
        op[(size_t)(2 * c) * 65536]     = v0;
        op[(size_t)(2 * c + 1) * 65536] = v1;
    }
}

// ----------------- head: fused fc1v + fc1t + gelu + fc2t -----------------
__global__ void __launch_bounds__(256) head_kernel(const float* __restrict__ vw,
                                                   const float* __restrict__ vb,
                                                   const float* __restrict__ b1,
                                                   const float* __restrict__ w2,
                                                   const float* __restrict__ b2,
                                                   float* __restrict__ dout) {
    __shared__ float sW1T[8192];
    __shared__ float sW2[2560];
    __shared__ float sB1h[256];
    int tid = threadIdx.x;
    for (int e = tid; e < 8192; e += 256) sW1T[e] = g_W1T[e];
    for (int e = tid; e < 2560; e += 256) sW2[e] = w2[e];
    sB1h[tid] = b1[tid];
    __syncthreads();
    int q = blockIdx.x * 256 + tid;
    int bvo = q >> 16, p = q & 65535;
    int b = bvo / 3, vo = bvo - 3 * b;
    float w0 = __ldg(&vw[vo]), w1 = __ldg(&vw[3 + vo]), w2v = __ldg(&vw[6 + vo]);
    float vbias = __ldg(&vb[vo]);
    const float* h0 = g_hA + (size_t)(b * 3 + 0) * 2097152 + p;
    const float* h1 = g_hA + (size_t)(b * 3 + 1) * 2097152 + p;
    const float* h2 = g_hA + (size_t)(b * 3 + 2) * 2097152 + p;
    float a[32];
#pragma unroll
    for (int c = 0; c < 32; c++) {
        float t = h0[(size_t)c * 65536] * w0 + h1[(size_t)c * 65536] * w1
                + h2[(size_t)c * 65536] * w2v + vbias;
        a[c] = gelu_f(t);
    }
    u64 ap[16];
#pragma unroll
    for (int c = 0; c < 16; c++) ap[c] = pk2(a[2 * c], a[2 * c + 1]);
    u64 o2[5];
#pragma unroll
    for (int s = 0; s < 5; s++) o2[s] = pk2(__ldg(&b2[2 * s]), __ldg(&b2[2 * s + 1]));
    for (int j = 0; j < 256; j++) {
        u64 ua = pk2(sB1h[j], 0.f);
        u64 ub = 0ull;
        const longlong2* wp = (const longlong2*)&sW1T[j * 32];
#pragma unroll
        for (int q2 = 0; q2 < 8; q2++) {
            longlong2 wv = wp[q2];
            ua = fma2((u64)wv.x, ap[2 * q2], ua);
            ub = fma2((u64)wv.y, ap[2 * q2 + 1], ub);
        }
        float l0, h0v, l1, h1v;
        upk2(ua, l0, h0v); upk2(ub, l1, h1v);
        float g = gelu_f((l0 + h0v) + (l1 + h1v));
        u64 gg = pk2(g, g);
        const u64* w2p = (const u64*)&sW2[j * 10];
#pragma unroll
        for (int s = 0; s < 5; s++) o2[s] = fma2(w2p[s], gg, o2[s]);
    }
    float2* op = (float2*)(dout + (size_t)bvo * 655360 + (size_t)p * 10);
#pragma unroll
    for (int s = 0; s < 5; s++) {
        float lo, hi;
        upk2(o2[s], lo, hi);
        op[s] = make_float2(lo, hi);
    }
}

// ----------------- launch -----------------
extern "C" void kernel_launch(void* const* d_in, const int* in_sizes, int n_in,
                              void* d_out, int out_size) {
    const float* x      = (const float*)d_in[0];
    const float* fc0_w  = (const float*)d_in[1];
    const float* fc0_b  = (const float*)d_in[2];
    const float* w1r    = (const float*)d_in[3];
    const float* w1i    = (const float*)d_in[4];
    const float* w2r    = (const float*)d_in[5];
    const float* w2i    = (const float*)d_in[6];
    const float* m1w    = (const float*)d_in[7];
    const float* m1b    = (const float*)d_in[8];
    const float* m2w    = (const float*)d_in[9];
    const float* m2b    = (const float*)d_in[10];
    const float* ww     = (const float*)d_in[11];
    const float* wb     = (const float*)d_in[12];
    const float* bw     = (const float*)d_in[13];
    const float* bb     = (const float*)d_in[14];
    const float* fc1v_w = (const float*)d_in[15];
    const float* fc1v_b = (const float*)d_in[16];
    const float* fc1t_w = (const float*)d_in[17];
    const float* fc1t_b = (const float*)d_in[18];
    const float* fc2t_w = (const float*)d_in[19];
    const float* fc2t_b = (const float*)d_in[20];
    float* out = (float*)d_out;

    setup_basis<<<48, 256>>>();
    transposeW1<<<32, 256>>>(fc1t_w);
    fc0_kernel<<<3072, 256>>>(x, fc0_w, fc0_b);

    const int tin[6]  = {0, 1, 2, 0, 1, 2};
    const int tout[6] = {1, 2, 0, 1, 2, 0};
    const int tres[6] = {-1, -1, 1, -1, -1, 1};
    for (int l = 0; l < 6; l++) {
        gemmF1_t<<<768, 256>>>(tin[l]);
        dftxF_t<<<384, 256>>>();
        mixmodes<<<768, 256>>>(w1r + (size_t)l * 786432, w1i + (size_t)l * 786432,
                               w2r + (size_t)l * 786432, w2i + (size_t)l * 786432);
        dftxI_t<<<384, 256>>>();
        convspec<<<3072, 256>>>(tin[l], tres[l], tout[l],
                                m1w + l * 1024, m1b + l * 32,
                                m2w + l * 1024, m2b + l * 32,
                                ww + l * 1024,  wb + l * 32,
                                bw + l * 64,    bb + l * 32);
    }
    head_kernel<<<3072, 256>>>(fc1v_w, fc1v_b, fc1t_b, fc2t_w, fc2t_b, out);
}

// round 13
// speedup vs baseline: 1.2670x; 1.0538x over previous
#include <cuda_runtime.h>
#include <math.h>

#define HBUF 25165824   // 12*32*65536 floats, channel-major [bv][c][p]

__device__ float g_hA[HBUF];
__device__ float g_hB[HBUF];
__device__ float g_hC[HBUF];
__device__ float g_spec[HBUF];
__device__ float g_Y[3145728];    // [row=bvc*256+x][32]  parity-permuted cols
__device__ float g_Z[3145728];    // [row=bvo*256+x][32]  (16 gr | 16 gi)
__device__ float g_X1[393216];
__device__ float g_X2[393216];
__device__ float g_Ef[8192];      // [y][32]: k<16 cos, k>=16 -sin
__device__ float g_Dy[8192];      // [j32][y] inverse-y real basis
__device__ float g_E2P[8192];     // [x128][m64] parity-permuted fwd-x basis
__device__ float g_EIP[8192];     // [kk64][x128] parity-permuted inv-x basis /256
__device__ float g_W1T[8192];     // fc1t_w transposed [j256][c32]

typedef unsigned long long u64;

__device__ __forceinline__ u64 pk2(float lo, float hi) {
    u64 r; asm("mov.b64 %0,{%1,%2};" : "=l"(r) : "f"(lo), "f"(hi)); return r;
}
__device__ __forceinline__ void upk2(u64 v, float& lo, float& hi) {
    asm("mov.b64 {%0,%1},%2;" : "=f"(lo), "=f"(hi) : "l"(v));
}
__device__ __forceinline__ u64 fma2(u64 a, u64 b, u64 c) {
    u64 d; asm("fma.rn.f32x2 %0,%1,%2,%3;" : "=l"(d) : "l"(a), "l"(b), "l"(c)); return d;
}
__device__ __forceinline__ float gelu_f(float x) {
    return 0.5f * x * (1.0f + erff(x * 0.70710678118654752440f));
}
__device__ __forceinline__ float* bufsel(int s) {
    if (s == 0) return g_hA;
    if (s == 1) return g_hB;
    if (s == 2) return g_hC;
    return g_spec;
}

// ----------------- basis tables -----------------
__global__ void setup_basis() {
    int x = threadIdx.x;
    int t = blockIdx.x;
    if (t < 16) {
        int k = t;
        double sv, cv;
        sincospi(((double)(k * x)) / 128.0, &sv, &cv);
        g_Ef[x * 32 + k]      = (float)cv;
        g_Ef[x * 32 + 16 + k] = (float)(-sv);
        double cj = (k == 0) ? 1.0 : 2.0;
        g_Dy[k * 256 + x]        = (float)( cj * cv / 256.0);
        g_Dy[(16 + k) * 256 + x] = (float)(-cj * sv / 256.0);
    } else {
        int j = t - 16;
        int f = (j < 16) ? j : (224 + j);
        double sv, cv;
        sincospi(((double)(f * x)) / 128.0, &sv, &cv);
        if (x < 128) {
            int p = j & 1, jh = j >> 1;
            g_E2P[x * 64 + p * 32 + jh]      = (float)cv;
            g_E2P[x * 64 + p * 32 + 16 + jh] = (float)sv;
            int base = p * 32 + jh * 2;
            g_EIP[base * 128 + x]       = (float)(cv / 256.0);
            g_EIP[(base + 1) * 128 + x] = (float)(sv / 256.0);
        }
    }
}

__global__ void transposeW1(const float* __restrict__ w) {
    int t = blockIdx.x * 256 + threadIdx.x;
    int c = t >> 8, j = t & 255;
    g_W1T[j * 32 + c] = w[t];
}

// ----------------- fc0 lift (channel-major out) -----------------
__global__ void __launch_bounds__(256) fc0_kernel(const float* __restrict__ xin,
                                                  const float* __restrict__ w,
                                                  const float* __restrict__ b) {
    __shared__ float sW[384];
    __shared__ float sB[32];
    int tid = threadIdx.x;
    for (int i = tid; i < 384; i += 256) sW[i] = w[i];
    if (tid < 32) sB[tid] = b[tid];
    __syncthreads();
    int q = blockIdx.x * 256 + tid;
    int bv = q >> 16, p = q & 65535;
    float xv[12];
    const float* xp = xin + (size_t)q * 10;
#pragma unroll
    for (int t = 0; t < 10; t++) xv[t] = xp[t];
    xv[10] = (float)(p >> 8) * (1.0f / 255.0f);
    xv[11] = (float)(p & 255) * (1.0f / 255.0f);
    float* out = g_hA + (size_t)bv * 2097152 + p;
#pragma unroll
    for (int c = 0; c < 32; c++) {
        float acc = sB[c];
#pragma unroll
        for (int t = 0; t < 12; t++) acc += xv[t] * sW[t * 32 + c];
        out[(size_t)c * 65536] = acc;
    }
}

// ----------------- F1: y-DFT with parity fold (y <-> y+128), K=128 -----------------
__global__ void __launch_bounds__(256) gemmF1_t(int s_in) {
    const float* __restrict__ A = bufsel(s_in);
    __shared__ float sAe[32 * 132];
    __shared__ float sAo[32 * 132];
    __shared__ float sEp[32 * 36];
    int tid = threadIdx.x;
    size_t rb = (size_t)blockIdx.x * 128;
    int r0 = (tid >> 3) * 4, c0 = (tid & 7) * 4;
    int lr = tid >> 1, lh = tid & 1;
    const float* sA = ((tid & 7) < 4) ? sAe : sAo;
    u64 acc2[2][4];
#pragma unroll
    for (int i = 0; i < 2; i++)
#pragma unroll
        for (int j = 0; j < 4; j++) acc2[i][j] = 0ull;

    for (int kt = 0; kt < 4; kt++) {
        __syncthreads();
        const float* Arow = A + (rb + lr) * 256 + kt * 32 + lh * 16;
#pragma unroll
        for (int i = 0; i < 4; i++) {
            float4 fa = *(const float4*)(Arow + i * 4);
            float4 fb = *(const float4*)(Arow + 128 + i * 4);
            int yy = lh * 16 + i * 4;
            sAe[(yy + 0) * 132 + lr] = fa.x + fb.x;
            sAo[(yy + 0) * 132 + lr] = fa.x - fb.x;
            sAe[(yy + 1) * 132 + lr] = fa.y + fb.y;
            sAo[(yy + 1) * 132 + lr] = fa.y - fb.y;
            sAe[(yy + 2) * 132 + lr] = fa.z + fb.z;
            sAo[(yy + 2) * 132 + lr] = fa.z - fb.z;
            sAe[(yy + 3) * 132 + lr] = fa.w + fb.w;
            sAo[(yy + 3) * 132 + lr] = fa.w - fb.w;
        }
#pragma unroll
        for (int i = 0; i < 4; i++) {
            int e = tid + i * 256;
            int u = e >> 5, m = e & 31;
            int col = ((m >> 3) & 1) * 16 + 2 * (m & 7) + (m >> 4);
            sEp[u * 36 + m] = g_Ef[(kt * 32 + u) * 32 + col];
        }
        __syncthreads();
#pragma unroll
        for (int kk = 0; kk < 32; kk++) {
            longlong2 la = *(const longlong2*)&sA[kk * 132 + r0];
            float4 e4 = *(const float4*)&sEp[kk * 36 + c0];
            u64 a0 = (u64)la.x, a1 = (u64)la.y;
            u64 eb[4] = {pk2(e4.x, e4.x), pk2(e4.y, e4.y), pk2(e4.z, e4.z), pk2(e4.w, e4.w)};
#pragma unroll
            for (int j = 0; j < 4; j++) {
                acc2[0][j] = fma2(a0, eb[j], acc2[0][j]);
                acc2[1][j] = fma2(a1, eb[j], acc2[1][j]);
            }
        }
    }
#pragma unroll
    for (int i = 0; i < 2; i++) {
        float lo0, hi0, lo1, hi1, lo2, hi2, lo3, hi3;
        upk2(acc2[i][0], lo0, hi0); upk2(acc2[i][1], lo1, hi1);
        upk2(acc2[i][2], lo2, hi2); upk2(acc2[i][3], lo3, hi3);
        *(float4*)&g_Y[(rb + r0 + 2 * i) * 32 + c0]     = make_float4(lo0, lo1, lo2, lo3);
        *(float4*)&g_Y[(rb + r0 + 2 * i + 1) * 32 + c0] = make_float4(hi0, hi1, hi2, hi3);
    }
}

// ----------------- F2: x-DFT, x-parity SPLIT across blocks (768 blocks) -----------------
__global__ void __launch_bounds__(256) dftxF_s() {
    __shared__ float sYp[4096];      // this block's parity fold [x<128][32]
    __shared__ float sO[32 * 33];    // this parity's 32 m-rows
    int tid = threadIdx.x;
    int bvc = blockIdx.x >> 1, par = blockIdx.x & 1;
    const float4* Yg = (const float4*)g_Y + (size_t)bvc * 2048;
    float sgn = par ? -1.f : 1.f;
#pragma unroll
    for (int i = 0; i < 4; i++) {
        int e = tid + i * 256;
        float4 a = Yg[e];
        float4 b = Yg[e + 1024];
        ((float4*)sYp)[e] = make_float4(a.x + sgn * b.x, a.y + sgn * b.y,
                                        a.z + sgn * b.z, a.w + sgn * b.w);
    }
    __syncthreads();
    int m0l = (tid >> 4) * 2, c0 = (tid & 15) * 2;
    int m0 = par * 32 + m0l;
    u64 acc2[2] = {0ull, 0ull};
#pragma unroll 8
    for (int kk = 0; kk < 128; kk++) {
        u64 am = *(const u64*)&g_E2P[kk * 64 + m0];
        float2 yv = *(const float2*)&sYp[kk * 32 + c0];
        acc2[0] = fma2(am, pk2(yv.x, yv.x), acc2[0]);
        acc2[1] = fma2(am, pk2(yv.y, yv.y), acc2[1]);
    }
#pragma unroll
    for (int j = 0; j < 2; j++) {
        float lo, hi;
        upk2(acc2[j], lo, hi);
        sO[m0l * 33 + c0 + j] = lo;
        sO[(m0l + 1) * 33 + c0 + j] = hi;
    }
    __syncthreads();
    int c = bvc & 31, bv = bvc >> 5;
    int b = bv / 3, v = bv - 3 * b;
    // this block emits the 16 kx with kx&1 == par (local cos row kxl, sin kxl+16)
    int kxl = tid >> 4, ky = tid & 15;
    int kx = 2 * kxl + par;
    int pe = (ky & 1) * 16 + (ky >> 1);
    int pi = pe + 8;
    float re = sO[kxl * 33 + pe] + sO[(16 + kxl) * 33 + pi];
    float im = sO[kxl * 33 + pi] - sO[(16 + kxl) * 33 + pe];
    ((float2*)g_X1)[(size_t)(v * 32 + kx) * 2048 + ky * 128 + b * 32 + c] = make_float2(re, im);
}

// ----------------- MIX -----------------
__global__ void __launch_bounds__(256) mixmodes(const float* __restrict__ w1r,
                                                const float* __restrict__ w1i,
                                                const float* __restrict__ w2r,
                                                const float* __restrict__ w2i) {
    __shared__ float2 sXc[2048];
    __shared__ float sWr[2048], sWi[2048];
    int tid = threadIdx.x;
    int bx = blockIdx.x;
    int v = bx >> 8, kx = (bx >> 3) & 31, oc = bx & 7;
    int mx = (kx < 16) ? kx : (kx - 16);
    const float* wr = (kx < 16) ? w1r : w2r;
    const float* wi = (kx < 16) ? w1i : w2i;
    const float2* x1f2 = (const float2*)g_X1;
    for (int e = tid; e < 2048; e += 256) {
        int ky = e >> 7, b = (e >> 5) & 3, i = e & 31;
        sXc[i * 64 + ky * 4 + b] = x1f2[(size_t)(v * 32 + kx) * 2048 + e];
    }
    for (int e = tid; e < 2048; e += 256) {
        int i = e >> 6, oo = (e >> 4) & 3, my = e & 15;
        size_t src = (size_t)i * 24576 + (size_t)(oc * 4 + oo) * 768 + v * 256 + mx * 16 + my;
        sWr[e] = wr[src];
        sWi[e] = wi[src];
    }
    __syncthreads();
    int o_ = tid >> 6, ky = (tid >> 2) & 15, b = tid & 3;
    float zr = 0.f, zi = 0.f;
#pragma unroll
    for (int i = 0; i < 32; i++) {
        float wrv = sWr[i * 64 + o_ * 16 + ky];
        float wiv = sWi[i * 64 + o_ * 16 + ky];
        float2 xv = sXc[i * 64 + ky * 4 + b];
        zr += xv.x * wrv - xv.y * wiv;
        zi += xv.x * wiv + xv.y * wrv;
    }
    int og = oc * 4 + o_;
    int bvo = (b * 3 + v) * 32 + og;
    ((float2*)g_X2)[(bvo * 32 + kx) * 16 + ky] = make_float2(zr, zi);
}

// ----------------- I1: inverse x-DFT, x-range SPLIT across blocks (768 blocks) -----------------
__global__ void __launch_bounds__(256) dftxI_s() {
    __shared__ float sGp[64 * 32];
    int tid = threadIdx.x;
    int bvo = blockIdx.x >> 1, half = blockIdx.x & 1;
    const float2* F = (const float2*)g_X2 + (size_t)bvo * 512;
#pragma unroll
    for (int t = tid; t < 512; t += 256) {
        int kx = t >> 4, ky = t & 15;
        float2 f = F[t];
        int base = (kx & 1) * 32 + (kx >> 1) * 2;
        sGp[base * 32 + ky]            = f.x;
        sGp[base * 32 + 16 + ky]       = f.y;
        sGp[(base + 1) * 32 + ky]      = -f.y;
        sGp[(base + 1) * 32 + 16 + ky] = f.x;
    }
    __syncthreads();
    int x0 = half * 64 + (tid >> 3) * 2, c0 = (tid & 7) * 4;
    u64 accE[4], accO[4];
#pragma unroll
    for (int j = 0; j < 4; j++) { accE[j] = 0ull; accO[j] = 0ull; }
#pragma unroll 8
    for (int kk = 0; kk < 32; kk++) {
        u64 a0 = *(const u64*)&g_EIP[kk * 128 + x0];
        float4 d = *(const float4*)&sGp[kk * 32 + c0];
        u64 db[4] = {pk2(d.x, d.x), pk2(d.y, d.y), pk2(d.z, d.z), pk2(d.w, d.w)};
#pragma unroll
        for (int j = 0; j < 4; j++) accE[j] = fma2(a0, db[j], accE[j]);
    }
#pragma unroll 8
    for (int kk = 32; kk < 64; kk++) {
        u64 a0 = *(const u64*)&g_EIP[kk * 128 + x0];
        float4 d = *(const float4*)&sGp[kk * 32 + c0];
        u64 db[4] = {pk2(d.x, d.x), pk2(d.y, d.y), pk2(d.z, d.z), pk2(d.w, d.w)};
#pragma unroll
        for (int j = 0; j < 4; j++) accO[j] = fma2(a0, db[j], accO[j]);
    }
    float el[4], eh[4], ol[4], oh[4];
#pragma unroll
    for (int j = 0; j < 4; j++) {
        upk2(accE[j], el[j], eh[j]);
        upk2(accO[j], ol[j], oh[j]);
    }
    size_t row0 = (size_t)bvo * 256 + x0;
    *(float4*)&g_Z[row0 * 32 + c0] =
        make_float4(el[0] + ol[0], el[1] + ol[1], el[2] + ol[2], el[3] + ol[3]);
    *(float4*)&g_Z[(row0 + 128) * 32 + c0] =
        make_float4(el[0] - ol[0], el[1] - ol[1], el[2] - ol[2], el[3] - ol[3]);
    *(float4*)&g_Z[(row0 + 1) * 32 + c0] =
        make_float4(eh[0] + oh[0], eh[1] + oh[1], eh[2] + oh[2], eh[3] + oh[3]);
    *(float4*)&g_Z[(row0 + 129) * 32 + c0] =
        make_float4(eh[0] - oh[0], eh[1] - oh[1], eh[2] - oh[2], eh[3] - oh[3]);
}

// ----------------- I2: inverse y-DFT with parity fold (round-10 form) -----------------
__global__ void __launch_bounds__(256) idfty_t() {
    __shared__ float sZe[16 * 68], sZo[16 * 68];
    __shared__ float sDe[16 * 68], sDo[16 * 68];
    int tid = threadIdx.x;
    size_t rb = (size_t)(blockIdx.x >> 1) * 64;
    int cb = (blockIdx.x & 1) * 64;
#pragma unroll
    for (int i = 0; i < 2; i++) {
        int e = tid + i * 256;
        int row = e >> 3, qd = e & 7;
        float4 f = *(const float4*)&g_Z[(rb + row) * 32 + qd * 4];
        sZe[(2 * qd) * 68 + row]     = f.x;
        sZo[(2 * qd) * 68 + row]     = f.y;
        sZe[(2 * qd + 1) * 68 + row] = f.z;
        sZo[(2 * qd + 1) * 68 + row] = f.w;
    }
#pragma unroll
    for (int i = 0; i < 8; i++) {
        int e = tid + i * 256;
        int par = e >> 10, rem = e & 1023;
        int jj = rem >> 6, cq = rem & 63;
        float vdy = g_Dy[(2 * jj + par) * 256 + cb + cq];
        if (par) sDo[jj * 68 + cq] = vdy; else sDe[jj * 68 + cq] = vdy;
    }
    __syncthreads();
    int r0 = (tid >> 4) * 4, c0 = (tid & 15) * 4;
    u64 accE[2][4], accO[2][4];
#pragma unroll
    for (int i = 0; i < 2; i++)
#pragma unroll
        for (int j = 0; j < 4; j++) { accE[i][j] = 0ull; accO[i][j] = 0ull; }
#pragma unroll
    for (int jj = 0; jj < 16; jj++) {
        longlong2 za = *(const longlong2*)&sZe[jj * 68 + r0];
        float4 d = *(const float4*)&sDe[jj * 68 + c0];
        u64 z0 = (u64)za.x, z1 = (u64)za.y;
        u64 db[4] = {pk2(d.x, d.x), pk2(d.y, d.y), pk2(d.z, d.z), pk2(d.w, d.w)};
#pragma unroll
        for (int j = 0; j < 4; j++) {
            accE[0][j] = fma2(z0, db[j], accE[0][j]);
            accE[1][j] = fma2(z1, db[j], accE[1][j]);
        }
    }
#pragma unroll
    for (int jj = 0; jj < 16; jj++) {
        longlong2 za = *(const longlong2*)&sZo[jj * 68 + r0];
        float4 d = *(const float4*)&sDo[jj * 68 + c0];
        u64 z0 = (u64)za.x, z1 = (u64)za.y;
        u64 db[4] = {pk2(d.x, d.x), pk2(d.y, d.y), pk2(d.z, d.z), pk2(d.w, d.w)};
#pragma unroll
        for (int j = 0; j < 4; j++) {
            accO[0][j] = fma2(z0, db[j], accO[0][j]);
            accO[1][j] = fma2(z1, db[j], accO[1][j]);
        }
    }
#pragma unroll
    for (int i = 0; i < 2; i++) {
        float e0l, e0h, e1l, e1h, e2l, e2h, e3l, e3h;
        float o0l, o0h, o1l, o1h, o2l, o2h, o3l, o3h;
        upk2(accE[i][0], e0l, e0h); upk2(accE[i][1], e1l, e1h);
        upk2(accE[i][2], e2l, e2h); upk2(accE[i][3], e3l, e3h);
        upk2(accO[i][0], o0l, o0h); upk2(accO[i][1], o1l, o1h);
        upk2(accO[i][2], o2l, o2h); upk2(accO[i][3], o3l, o3h);
        size_t row0 = rb + r0 + 2 * i;
        size_t row1 = row0 + 1;
        *(float4*)&g_spec[row0 * 256 + cb + c0] =
            make_float4(e0l + o0l, e1l + o1l, e2l + o2l, e3l + o3l);
        *(float4*)&g_spec[row0 * 256 + cb + c0 + 128] =
            make_float4(e0l - o0l, e1l - o1l, e2l - o2l, e3l - o3l);
        *(float4*)&g_spec[row1 * 256 + cb + c0] =
            make_float4(e0h + o0h, e1h + o1h, e2h + o2h, e3h + o3h);
        *(float4*)&g_spec[row1 * 256 + cb + c0 + 128] =
            make_float4(e0h - o0h, e1h - o1h, e2h - o2h, e3h - o3h);
    }
}

// ----------------- fused pointwise chain (round-10 form) -----------------
__global__ void __launch_bounds__(256) convfuse(int s_t, int s_res, int s_out,
        const float* __restrict__ m1w, const float* __restrict__ m1b,
        const float* __restrict__ m2w, const float* __restrict__ m2b,
        const float* __restrict__ ww,  const float* __restrict__ wb,
        const float* __restrict__ bw,  const float* __restrict__ bb) {
    __shared__ float sM1[1024], sM2T[1024], sWW[1024];
    __shared__ float sB1[32], sB0[32], sBX[32], sBY[32];
    int tid = threadIdx.x;
    for (int e = tid; e < 1024; e += 256) {
        sM1[e] = m1w[e];
        sWW[e] = ww[e];
        sM2T[(e & 31) * 32 + (e >> 5)] = m2w[e];
    }
    if (tid < 32) {
        sB1[tid] = m1b[tid];
        sB0[tid] = m2b[tid] + wb[tid] + bb[tid];
        sBX[tid] = bw[tid * 2];
        sBY[tid] = bw[tid * 2 + 1];
    }
    __syncthreads();
    int q = blockIdx.x * 256 + tid;
    int bv = q >> 16, p = q & 65535;
    float gx = (float)(p >> 8) * (1.0f / 255.0f);
    float gy = (float)(p & 255) * (1.0f / 255.0f);
    size_t base = (size_t)bv * 2097152 + p;
    const float* tp = bufsel(s_t) + base;
    u64 ap[16];
#pragma unroll
    for (int c = 0; c < 16; c++)
        ap[c] = pk2(tp[(size_t)(2 * c) * 65536], tp[(size_t)(2 * c + 1) * 65536]);
    u64 acc2[16];
#pragma unroll
    for (int oq = 0; oq < 16; oq++) {
        float rr0, rr1;
#pragma unroll
        for (int h = 0; h < 2; h++) {
            int o = 2 * oq + h;
            u64 sa = pk2(sB0[o] + sBX[o] * gx + sBY[o] * gy, 0.f);
            u64 sb = 0ull;
            const longlong2* wp = (const longlong2*)&sWW[o * 32];
#pragma unroll
            for (int q2 = 0; q2 < 8; q2++) {
                longlong2 wv = wp[q2];
                sa = fma2((u64)wv.x, ap[2 * q2], sa);
                sb = fma2((u64)wv.y, ap[2 * q2 + 1], sb);
            }
            float l0, h0, l1, h1;
            upk2(sa, l0, h0); upk2(sb, l1, h1);
            float r = (l0 + h0) + (l1 + h1);
            if (h == 0) rr0 = r; else rr1 = r;
        }
        acc2[oq] = pk2(rr0, rr1);
    }
    const float* spp = g_spec + base;
#pragma unroll
    for (int c = 0; c < 16; c++)
        ap[c] = pk2(spp[(size_t)(2 * c) * 65536], spp[(size_t)(2 * c + 1) * 65536]);
#pragma unroll
    for (int o = 0; o < 32; o++) {
        u64 sa = pk2(sB1[o], 0.f);
        u64 sb = 0ull;
        const longlong2* wp = (const longlong2*)&sM1[o * 32];
#pragma unroll
        for (int q2 = 0; q2 < 8; q2++) {
            longlong2 wv = wp[q2];
            sa = fma2((u64)wv.x, ap[2 * q2], sa);
            sb = fma2((u64)wv.y, ap[2 * q2 + 1], sb);
        }
        float l0, h0, l1, h1;
        upk2(sa, l0, h0); upk2(sb, l1, h1);
        float g = gelu_f((l0 + h0) + (l1 + h1));
        u64 gg = pk2(g, g);
        const longlong2* mp = (const longlong2*)&sM2T[o * 32];
#pragma unroll
        for (int q2 = 0; q2 < 8; q2++) {
            longlong2 mv = mp[q2];
            acc2[2 * q2]     = fma2((u64)mv.x, gg, acc2[2 * q2]);
            acc2[2 * q2 + 1] = fma2((u64)mv.y, gg, acc2[2 * q2 + 1]);
        }
    }
    float* op = bufsel(s_out) + base;
    const float* rp = (s_res >= 0) ? (bufsel(s_res) + base) : (const float*)0;
#pragma unroll
    for (int c = 0; c < 16; c++) {
        float lo, hi;
        upk2(acc2[c], lo, hi);
        float v0 = gelu_f(lo), v1 = gelu_f(hi);
        if (rp) {
            v0 += rp[(size_t)(2 * c) * 65536];
            v1 += rp[(size_t)(2 * c + 1) * 65536];
        }
        op[(size_t)(2 * c) * 65536]     = v0;
        op[(size_t)(2 * c + 1) * 65536] = v1;
    }
}

// ----------------- head: fused fc1v + fc1t + gelu + fc2t (round-10 form) -----------------
__global__ void __launch_bounds__(256) head_kernel(const float* __restrict__ vw,
                                                   const float* __restrict__ vb,
                                                   const float* __restrict__ b1,
                                                   const float* __restrict__ w2,
                                                   const float* __restrict__ b2,
                                                   float* __restrict__ dout) {
    __shared__ float sW1T[8192];
    __shared__ float sW2[2560];
    __shared__ float sB1h[256];
    int tid = threadIdx.x;
    for (int e = tid; e < 8192; e += 256) sW1T[e] = g_W1T[e];
    for (int e = tid; e < 2560; e += 256) sW2[e] = w2[e];
    sB1h[tid] = b1[tid];
    __syncthreads();
    int q = blockIdx.x * 256 + tid;
    int bvo = q >> 16, p = q & 65535;
    int b = bvo / 3, vo = bvo - 3 * b;
    float w0 = __ldg(&vw[vo]), w1 = __ldg(&vw[3 + vo]), w2v = __ldg(&vw[6 + vo]);
    float vbias = __ldg(&vb[vo]);
    const float* h0 = g_hA + (size_t)(b * 3 + 0) * 2097152 + p;
    const float* h1 = g_hA + (size_t)(b * 3 + 1) * 2097152 + p;
    const float* h2 = g_hA + (size_t)(b * 3 + 2) * 2097152 + p;
    float a[32];
#pragma unroll
    for (int c = 0; c < 32; c++) {
        float t = h0[(size_t)c * 65536] * w0 + h1[(size_t)c * 65536] * w1
                + h2[(size_t)c * 65536] * w2v + vbias;
        a[c] = gelu_f(t);
    }
    u64 ap[16];
#pragma unroll
    for (int c = 0; c < 16; c++) ap[c] = pk2(a[2 * c], a[2 * c + 1]);
    u64 o2[5];
#pragma unroll
    for (int s = 0; s < 5; s++) o2[s] = pk2(__ldg(&b2[2 * s]), __ldg(&b2[2 * s + 1]));
    for (int j = 0; j < 256; j++) {
        u64 ua = pk2(sB1h[j], 0.f);
        u64 ub = 0ull;
        const longlong2* wp = (const longlong2*)&sW1T[j * 32];
#pragma unroll
        for (int q2 = 0; q2 < 8; q2++) {
            longlong2 wv = wp[q2];
            ua = fma2((u64)wv.x, ap[2 * q2], ua);
            ub = fma2((u64)wv.y, ap[2 * q2 + 1], ub);
        }
        float l0, h0v, l1, h1v;
        upk2(ua, l0, h0v); upk2(ub, l1, h1v);
        float g = gelu_f((l0 + h0v) + (l1 + h1v));
        u64 gg = pk2(g, g);
        const u64* w2p = (const u64*)&sW2[j * 10];
#pragma unroll
        for (int s = 0; s < 5; s++) o2[s] = fma2(w2p[s], gg, o2[s]);
    }
    float2* op = (float2*)(dout + (size_t)bvo * 655360 + (size_t)p * 10);
#pragma unroll
    for (int s = 0; s < 5; s++) {
        float lo, hi;
        upk2(o2[s], lo, hi);
        op[s] = make_float2(lo, hi);
    }
}

// ----------------- launch -----------------
extern "C" void kernel_launch(void* const* d_in, const int* in_sizes, int n_in,
                              void* d_out, int out_size) {
    const float* x      = (const float*)d_in[0];
    const float* fc0_w  = (const float*)d_in[1];
    const float* fc0_b  = (const float*)d_in[2];
    const float* w1r    = (const float*)d_in[3];
    const float* w1i    = (const float*)d_in[4];
    const float* w2r    = (const float*)d_in[5];
    const float* w2i    = (const float*)d_in[6];
    const float* m1w    = (const float*)d_in[7];
    const float* m1b    = (const float*)d_in[8];
    const float* m2w    = (const float*)d_in[9];
    const float* m2b    = (const float*)d_in[10];
    const float* ww     = (const float*)d_in[11];
    const float* wb     = (const float*)d_in[12];
    const float* bw     = (const float*)d_in[13];
    const float* bb     = (const float*)d_in[14];
    const float* fc1v_w = (const float*)d_in[15];
    const float* fc1v_b = (const float*)d_in[16];
    const float* fc1t_w = (const float*)d_in[17];
    const float* fc1t_b = (const float*)d_in[18];
    const float* fc2t_w = (const float*)d_in[19];
    const float* fc2t_b = (const float*)d_in[20];
    float* out = (float*)d_out;

    setup_basis<<<48, 256>>>();
    transposeW1<<<32, 256>>>(fc1t_w);
    fc0_kernel<<<3072, 256>>>(x, fc0_w, fc0_b);

    const int tin[6]  = {0, 1, 2, 0, 1, 2};
    const int tout[6] = {1, 2, 0, 1, 2, 0};
    const int tres[6] = {-1, -1, 1, -1, -1, 1};
    for (int l = 0; l < 6; l++) {
        gemmF1_t<<<768, 256>>>(tin[l]);
        dftxF_s<<<768, 256>>>();
        mixmodes<<<768, 256>>>(w1r + (size_t)l * 786432, w1i + (size_t)l * 786432,
                               w2r + (size_t)l * 786432, w2i + (size_t)l * 786432);
        dftxI_s<<<768, 256>>>();
        idfty_t<<<3072, 256>>>();
        convfuse<<<3072, 256>>>(tin[l], tres[l], tout[l],
                                m1w + l * 1024, m1b + l * 32,
                                m2w + l * 1024, m2b + l * 32,
                                ww + l * 1024,  wb + l * 32,
                                bw + l * 64,    bb + l * 32);
    }
    head_kernel<<<3072, 256>>>(fc1v_w, fc1v_b, fc1t_b, fc2t_w, fc2t_b, out);
}